// round 4
// baseline (speedup 1.0000x reference)
#include <cuda_runtime.h>
#include <math.h>

#define C_B  8
#define C_J  22
#define C_F  14
#define A_MAX 7.25f
#define S_MAX 9.25f
#define SIG_K (3.14f / (1.732f * 0.5f))

// Single CTA (cheapest launch shape at this scale), 8 warps; warp b owns
// batch b, lane j owns player j. team[j] = (j < 11) by construction:
//   lanes 0..10  (attackers): s = rec_j * p_j, q = 1
//   lanes 11..21 (defenders): q = 1 - p_j,     s = 0
//   lanes 22..31: neutral (q=1, s=0)
// out[b] = (sum_j rec_j p_j) * prod_def(1 - p_j) + 1e-3  via one
// simultaneous (product, sum) warp butterfly. Approx intrinsics
// (rsqrtf/__expf/sqrtf) keep error ~1e-6 << 1e-3 tolerance; branchless
// select avoids BSSY/BSYNC on the serial chain.
__global__ void __launch_bounds__(256, 1)
comp_prob_kernel(const float* __restrict__ frame, float* __restrict__ out) {
    const int b = threadIdx.x >> 5;   // warp = batch
    const int j = threadIdx.x & 31;   // lane = player

    const float* row0 = frame + b * C_J * C_F;

    float q = 1.0f;
    float s = 0.0f;

    if (j < C_J) {
        const float* row = row0 + j * C_F;

        const float px = __ldg(row + 1), py = __ldg(row + 2);
        const float vx = __ldg(row + 3), vy = __ldg(row + 4);
        const float rec = (j < 11) ? __ldg(row + 10) : 0.0f;
        const float bxf = __ldg(row0 + 11);
        const float byf = __ldg(row0 + 12);
        const float tof = __ldg(row0 + 13);

        // Selected field cell: x = int(bx)+0.5, y = (int(by)+1)-0.5
        const float fx = (float)((int)bxf) + 0.5f;
        const float fy = (float)((int)byf) + 0.5f;   // (iy+1) - 0.5

        const float dx = fx - px;
        const float dy = fy - py;
        const float d2 = fmaf(dx, dx, dy * dy);
        const float invd = rsqrtf(d2);
        const float d = d2 * invd;

        float s0 = fmaf(dx, vx, dy * vy) * invd;
        s0 = fminf(fmaxf(s0, -S_MAX), S_MAX);

        // Arm A: reaches top speed
        const float t_lt1 = (S_MAX - s0) * (1.0f / A_MAX);
        const float d_lt1 = t_lt1 * (s0 + S_MAX) * 0.5f;
        // Arm B: doesn't
        const float sa = s0 * (1.0f / A_MAX);
        const float t_lt2 = sqrtf(fmaf(sa, sa, 2.0f * d * (1.0f / A_MAX))) - sa;

        const float t_lt = (d_lt1 > d) ? t_lt2 : t_lt1;
        const float d_lt = fminf(fmaxf(d_lt1, 0.0f), d);
        const float t_tot = fmaf(d - d_lt, 1.0f / S_MAX, t_lt);

        // T[round(tof)-1] = 0.1 * round(tof)
        const float Tt = 0.1f * rintf(tof);

        const float p = 1.0f / (1.0f + __expf(SIG_K * (t_tot - Tt)));

        if (j < 11) { s = rec * p; }   // attacker
        else        { q = 1.0f - p; }  // defender
    }

    #pragma unroll
    for (int o = 16; o > 0; o >>= 1) {
        q *= __shfl_xor_sync(0xFFFFFFFFu, q, o);
        s += __shfl_xor_sync(0xFFFFFFFFu, s, o);
    }

    if (j == 0) out[b] = fmaf(s, q, 0.001f);
}

extern "C" void kernel_launch(void* const* d_in, const int* in_sizes, int n_in,
                              void* d_out, int out_size) {
    comp_prob_kernel<<<1, 256>>>((const float*)d_in[0], (float*)d_out);
}